// round 5
// baseline (speedup 1.0000x reference)
#include <cuda_runtime.h>
#include <cuda_bf16.h>
#include <math.h>
#include <stdint.h>

// ---------------------------------------------------------------------------
// PoincareLinear via tcgen05 bf16 split GEMM (sm_103a) + SIMT fallback body
// for the non-'a' PTX stage.
//   dot = x_hi@w_hi + x_hi@w_lo + x_lo@w_hi   (K_eff = 3*1024)
//   256x256 output tile per CTA, 3-stage cp.async pipeline, commit-mbar reuse.
//   Epilogue: Poincare MLR math + per-row ||y||^2 partials; rescale kernel
//   applies gyro-half map + ball projection.
// ---------------------------------------------------------------------------

#if defined(__CUDA_ARCH_FEAT_SM103_ALL) || defined(__CUDA_ARCH_FEAT_SM100_ALL) || \
    defined(__CUDA_ARCH_SPECIFIC__) || defined(__CUDA_ARCH_FAMILY_SPECIFIC__)
#define HAS_TCGEN05 1
#else
#define HAS_TCGEN05 0
#endif

#define N_MAX   32768
#define IN_MAX  1024
#define OUT_MAX 1024

__device__ __nv_bfloat16 g_xhi[(size_t)N_MAX * IN_MAX];
__device__ __nv_bfloat16 g_xlo[(size_t)N_MAX * IN_MAX];
__device__ __nv_bfloat16 g_whi[(size_t)OUT_MAX * IN_MAX];   // [out][in], colscale folded
__device__ __nv_bfloat16 g_wlo[(size_t)OUT_MAX * IN_MAX];
__device__ float g_colscale[OUT_MAX];
__device__ float g_coshb[OUT_MAX];
__device__ float g_sinhb[OUT_MAX];
__device__ float g_cx2[N_MAX];
__device__ float g_ysq_part[(size_t)N_MAX * 4];   // per-row, per-col-CTA partial ||y||^2

constexpr uint64_t kSmemDescBaseSW128 =
    (uint64_t(2) << 61) | (uint64_t(1) << 46) | (uint64_t(64) << 32) | (uint64_t(1) << 16);

// ---------------- generic helpers -------------------------------------------
__device__ __forceinline__ uint32_t smem_u32(const void* p) {
    uint32_t a;
    asm("{ .reg .u64 t; cvta.to.shared.u64 t, %1; cvt.u32.u64 %0, t; }"
        : "=r"(a) : "l"(p));
    return a;
}
#define SW128(off) ((off) ^ (((off) >> 3) & 0x70))

__device__ __forceinline__ float block_reduce_sum(float v) {
    __shared__ float red[32];
    int lane = threadIdx.x & 31, wid = threadIdx.x >> 5;
    #pragma unroll
    for (int o = 16; o > 0; o >>= 1) v += __shfl_down_sync(0xffffffff, v, o);
    if (lane == 0) red[wid] = v;
    __syncthreads();
    int nw = (blockDim.x + 31) >> 5;
    v = (threadIdx.x < nw) ? red[threadIdx.x] : 0.f;
    if (wid == 0)
        #pragma unroll
        for (int o = 16; o > 0; o >>= 1) v += __shfl_down_sync(0xffffffff, v, o);
    return v;
}

#if HAS_TCGEN05
// ---------------- tcgen05 / mbarrier / cp.async wrappers ---------------------
__device__ __forceinline__ uint32_t elect_one() {
    uint32_t p;
    asm volatile("{ .reg .pred p; elect.sync _|p, 0xFFFFFFFF; selp.b32 %0,1,0,p; }"
                 : "=r"(p));
    return p;
}
__device__ __forceinline__ uint64_t make_desc(uint32_t addr) {
    return kSmemDescBaseSW128 | ((uint64_t)(addr >> 4) & 0x3FFF);
}
__device__ __forceinline__ void mbar_init(uint32_t a, uint32_t cnt) {
    asm volatile("mbarrier.init.shared.b64 [%0], %1;" :: "r"(a), "r"(cnt) : "memory");
}
__device__ __forceinline__ void mbar_wait(uint32_t a, uint32_t parity) {
    uint32_t done;
    asm volatile("{ .reg .pred p; mbarrier.try_wait.parity.acquire.cta.shared::cta.b64 p, [%1], %2;"
                 " selp.b32 %0,1,0,p; }" : "=r"(done) : "r"(a), "r"(parity) : "memory");
    if (!done) {
        asm volatile("{ .reg .pred P1; WL%=:"
                     " mbarrier.try_wait.parity.acquire.cta.shared::cta.b64 P1, [%0], %1, 0x989680;"
                     " @P1 bra.uni WD%=; bra.uni WL%=; WD%=: }"
                     :: "r"(a), "r"(parity) : "memory");
    }
}
__device__ __forceinline__ void tc_alloc(uint32_t smem_dst, uint32_t ncols) {
    asm volatile("tcgen05.alloc.cta_group::1.sync.aligned.shared::cta.b32 [%0], %1;"
                 :: "r"(smem_dst), "r"(ncols) : "memory");
}
__device__ __forceinline__ void tc_dealloc(uint32_t tmem, uint32_t ncols) {
    asm volatile("tcgen05.dealloc.cta_group::1.sync.aligned.b32 %0, %1;" :: "r"(tmem), "r"(ncols));
}
__device__ __forceinline__ void tc_relinquish() {
    asm volatile("tcgen05.relinquish_alloc_permit.cta_group::1.sync.aligned;");
}
__device__ __forceinline__ void tc_commit(uint32_t mbar) {
    asm volatile("tcgen05.commit.cta_group::1.mbarrier::arrive::one.shared::cluster.b64 [%0];"
                 :: "r"(mbar) : "memory");
}
__device__ __forceinline__ void mma_f16_ss(uint32_t d, uint64_t ad, uint64_t bd,
                                           uint32_t idesc, bool acc) {
    uint32_t en = acc ? 1u : 0u;
    asm volatile("{ .reg .pred p; setp.ne.u32 p, %4, 0;"
                 " tcgen05.mma.cta_group::1.kind::f16 [%0], %1, %2, %3, {%5,%5,%5,%5}, p; }"
                 :: "r"(d), "l"(ad), "l"(bd), "r"(idesc), "r"(en), "r"(0u) : "memory");
}
__device__ __forceinline__ void cp16(uint32_t dst, const void* src) {
    asm volatile("cp.async.cg.shared.global [%0], [%1], 16;" :: "r"(dst), "l"(src));
}
#define CP_COMMIT() asm volatile("cp.async.commit_group;" ::: "memory")
#define CP_WAIT2()  asm volatile("cp.async.wait_group 2;" ::: "memory")
#define TC_LD_X32(r, addr) \
    asm volatile("tcgen05.ld.sync.aligned.32x32b.x32.b32 " \
        "{%0,%1,%2,%3,%4,%5,%6,%7,%8,%9,%10,%11,%12,%13,%14,%15," \
        "%16,%17,%18,%19,%20,%21,%22,%23,%24,%25,%26,%27,%28,%29,%30,%31}, [%32];" \
        : "=r"((r)[0]),"=r"((r)[1]),"=r"((r)[2]),"=r"((r)[3]),"=r"((r)[4]),"=r"((r)[5]), \
          "=r"((r)[6]),"=r"((r)[7]),"=r"((r)[8]),"=r"((r)[9]),"=r"((r)[10]),"=r"((r)[11]), \
          "=r"((r)[12]),"=r"((r)[13]),"=r"((r)[14]),"=r"((r)[15]),"=r"((r)[16]),"=r"((r)[17]), \
          "=r"((r)[18]),"=r"((r)[19]),"=r"((r)[20]),"=r"((r)[21]),"=r"((r)[22]),"=r"((r)[23]), \
          "=r"((r)[24]),"=r"((r)[25]),"=r"((r)[26]),"=r"((r)[27]),"=r"((r)[28]),"=r"((r)[29]), \
          "=r"((r)[30]),"=r"((r)[31]) : "r"(addr))
#define TC_WAIT_LD()  asm volatile("tcgen05.wait::ld.sync.aligned;" ::: "memory")
#define TC_FENCE_AFTER()  asm volatile("tcgen05.fence::after_thread_sync;" ::: "memory")
#define TC_FENCE_BEFORE() asm volatile("tcgen05.fence::before_thread_sync;" ::: "memory")
#define FENCE_ASYNC_SHARED() asm volatile("fence.proxy.async.shared::cta;" ::: "memory")
#endif // HAS_TCGEN05

// ---------------- prep: colscale + cosh/sinh(2 rc b) -------------------------
__global__ void prep_kernel(const float* __restrict__ w, const float* __restrict__ bias,
                            const float* __restrict__ c_ptr, int IN, int OUT) {
    int o = blockIdx.x * blockDim.x + threadIdx.x;
    if (o >= OUT) return;
    float s = 0.f;
    for (int i = 0; i < IN; ++i) { float v = w[(size_t)i * OUT + o]; s = fmaf(v, v, s); }
    g_colscale[o] = 1.0f / fmaxf(sqrtf(s), 1e-15f);
    float rc = sqrtf(c_ptr[0]);
    float d = 2.0f * rc * bias[o];
    g_coshb[o] = coshf(d);
    g_sinhb[o] = sinhf(d);
}

// ---------------- transpose + scale + bf16 split of w ------------------------
__global__ void convert_w_kernel(const float* __restrict__ w, int IN, int OUT) {
    __shared__ float t[32][33];
    int n0 = blockIdx.x * 32, k0 = blockIdx.y * 32;
    int tx = threadIdx.x, ty = threadIdx.y;
    t[ty][tx] = w[(size_t)(k0 + ty) * OUT + n0 + tx];
    __syncthreads();
    int n = n0 + ty, k = k0 + tx;
    float v = t[tx][ty] * g_colscale[n];
    __nv_bfloat16 hi = __float2bfloat16(v);
    float r = v - __bfloat162float(hi);
    g_whi[(size_t)n * IN + k] = hi;
    g_wlo[(size_t)n * IN + k] = __float2bfloat16(r);
}

// ---------------- x -> bf16 hi/lo, fused cx2, zero ysq partials --------------
__global__ void convert_x_kernel(const float* __restrict__ x,
                                 const float* __restrict__ c_ptr, int IN) {
    int row = blockIdx.x;
    if (threadIdx.x < 4) g_ysq_part[(size_t)row * 4 + threadIdx.x] = 0.f;
    const float4* xr = (const float4*)(x + (size_t)row * IN);
    int n4 = IN >> 2;
    float s = 0.f;
    for (int i = threadIdx.x; i < n4; i += blockDim.x) {
        float4 v = xr[i];
        s = fmaf(v.x, v.x, s); s = fmaf(v.y, v.y, s);
        s = fmaf(v.z, v.z, s); s = fmaf(v.w, v.w, s);
        __nv_bfloat16 h0 = __float2bfloat16(v.x), h1 = __float2bfloat16(v.y);
        __nv_bfloat16 h2 = __float2bfloat16(v.z), h3 = __float2bfloat16(v.w);
        __nv_bfloat16 l0 = __float2bfloat16(v.x - __bfloat162float(h0));
        __nv_bfloat16 l1 = __float2bfloat16(v.y - __bfloat162float(h1));
        __nv_bfloat16 l2 = __float2bfloat16(v.z - __bfloat162float(h2));
        __nv_bfloat16 l3 = __float2bfloat16(v.w - __bfloat162float(h3));
        uint2 hp, lp;
        hp.x = ((uint32_t)__bfloat16_as_ushort(h1) << 16) | __bfloat16_as_ushort(h0);
        hp.y = ((uint32_t)__bfloat16_as_ushort(h3) << 16) | __bfloat16_as_ushort(h2);
        lp.x = ((uint32_t)__bfloat16_as_ushort(l1) << 16) | __bfloat16_as_ushort(l0);
        lp.y = ((uint32_t)__bfloat16_as_ushort(l3) << 16) | __bfloat16_as_ushort(l2);
        *(uint2*)(g_xhi + (size_t)row * IN + i * 4) = hp;
        *(uint2*)(g_xlo + (size_t)row * IN + i * 4) = lp;
    }
    float tot = block_reduce_sum(s);
    if (threadIdx.x == 0) g_cx2[row] = c_ptr[0] * tot;
}

// ---------------- GEMM + fused Poincare epilogue -----------------------------
#define MT 256
#define NT 256
#define KC 64
// per-dispatch M = 128
#define IDESC ((1u<<4) | (1u<<7) | (1u<<10) | ((NT/8u)<<17) | (8u<<24))

#define OFF_TMEM 0u
#define OFF_MB   8u                         // 3 mbarriers at 8,16,24
#define OFF_PAR  64u                        // 3 * NT floats = 3072 B
#define OFF_T    4096u
#define ASZ      (MT * 128u)                // 32 KB
#define BSZ      (NT * 128u)                // 32 KB
#define STAGE    (ASZ + BSZ)                // 64 KB
#define NSTAGE   3
#define SMEM_BYTES (OFF_T + NSTAGE * STAGE) // 200704

__global__ __launch_bounds__(256, 1)
void gemm_tc_kernel(const float* __restrict__ X, const float* __restrict__ W,
                    const float* __restrict__ wgp, const float* __restrict__ c_ptr,
                    float* __restrict__ out, int Nrows, int IN, int OUT) {
    extern __shared__ char smem[];
#if HAS_TCGEN05
    const uint32_t sb = smem_u32(smem);
    const int tid = threadIdx.x;
    const int wid = tid >> 5, lane = tid & 31;
    const int brow = blockIdx.y * MT, bcol = blockIdx.x * NT;
    const int nchunk = (3 * IN) / KC;   // 48

    if (wid == 0) { tc_alloc(sb + OFF_TMEM, 512); tc_relinquish(); }
    if (tid == 0) {
        mbar_init(sb + OFF_MB + 0, 1);
        mbar_init(sb + OFF_MB + 8, 1);
        mbar_init(sb + OFF_MB + 16, 1);
    }
    float* chb = (float*)(smem + OFF_PAR);
    float* shb = chb + NT;
    float* g2s = shb + NT;
    if (tid < NT) {
        int o = bcol + tid;
        chb[tid] = g_coshb[o];
        shb[tid] = g_sinhb[o];
        g2s[tid] = 2.0f * wgp[o];
    }
    __syncthreads();
    uint32_t tmem;
    asm volatile("ld.shared.b32 %0, [%1];" : "=r"(tmem) : "r"(sb + OFF_TMEM));

    // per-chunk segment select: 0..15 hi*hi, 16..31 hi*lo, 32..47 lo*hi
    auto issue_loads = [&](int c, int s) {
        const int seg = c >> 4;
        const int k0  = (c & 15) * KC;
        const __nv_bfloat16* srcA = (seg == 2) ? g_xlo : g_xhi;
        const __nv_bfloat16* srcB = (seg == 1) ? g_wlo : g_whi;
        const uint32_t Aoff = OFF_T + (uint32_t)s * STAGE;
        const uint32_t Boff = Aoff + ASZ;
        #pragma unroll
        for (int l = 0; l < 8; ++l) {
            int idx = tid + l * 256;            // 0..2047
            int r = idx >> 3, j = idx & 7;
            cp16(sb + Aoff + SW128((uint32_t)(r * 128 + j * 16)),
                 srcA + (size_t)(brow + r) * IN + k0 + j * 8);
        }
        #pragma unroll
        for (int l = 0; l < 8; ++l) {
            int idx = tid + l * 256;
            int r = idx >> 3, j = idx & 7;
            cp16(sb + Boff + SW128((uint32_t)(r * 128 + j * 16)),
                 srcB + (size_t)(bcol + r) * IN + k0 + j * 8);
        }
    };

    // prologue: stages 0..2 <- chunks 0..2
    for (int s = 0; s < NSTAGE; ++s) { issue_loads(s, s); CP_COMMIT(); }

    for (int c = 0; c < nchunk; ++c) {
        const int s = c % 3;
        CP_WAIT2();                 // chunk c resident
        FENCE_ASYNC_SHARED();
        __syncthreads();
        if (wid == 0 && elect_one()) {
            const uint32_t Aoff = OFF_T + (uint32_t)s * STAGE;
            uint64_t ad = make_desc(sb + Aoff);
            uint64_t bd = make_desc(sb + Aoff + ASZ);
            #pragma unroll
            for (int k = 0; k < 4; ++k) {
                bool acc = (c > 0) || (k > 0);
                mma_f16_ss(tmem,       ad + k * 2,        bd + k * 2, IDESC, acc);
                mma_f16_ss(tmem + 256, ad + 1024 + k * 2, bd + k * 2, IDESC, acc);
            }
            tc_commit(sb + OFF_MB + 8u * (uint32_t)s);
        }
        if (c + NSTAGE < nchunk) {
            // buffer s reused for chunk c+3: wait chunk c's MMAs to drain
            mbar_wait(sb + OFF_MB + 8u * (uint32_t)s, (uint32_t)((c / 3) & 1));
            issue_loads(c + NSTAGE, s);
        }
        CP_COMMIT();                // one group per iteration (may be empty)
    }
    // final commits: last per-stage commit index m = nchunk/3 - 1
    {
        uint32_t fp = (uint32_t)(((nchunk / 3) - 1) & 1);
        mbar_wait(sb + OFF_MB + 0, fp);
        mbar_wait(sb + OFF_MB + 8, fp);
        mbar_wait(sb + OFF_MB + 16, fp);
    }
    TC_FENCE_AFTER();

    // ---- epilogue: 8 warps; half = wid>>2 selects M-half / TMEM 256-col bank
    const float rc = sqrtf(c_ptr[0]);
    const float invrc = 1.0f / rc;
    const int half = wid >> 2, sub = wid & 3;
    const int row = brow + half * 128 + sub * 32 + lane;
    const float cx2 = g_cx2[row];
    const float invd = 1.0f / fmaxf(1.0f - cx2, 1e-15f);
    const float onep = 1.0f + cx2;
    const float two_rc = 2.0f * rc;
    float ysq = 0.f;

    #pragma unroll
    for (int cc = 0; cc < 4; ++cc) {
        const int cb = cc * 64;
        uint32_t d[64];
        TC_LD_X32(d, tmem + half * 256 + cb);
        TC_LD_X32(d + 32, tmem + half * 256 + cb + 32);
        TC_WAIT_LD();
        float* orow = out + (size_t)row * OUT + bcol + cb;
        #pragma unroll
        for (int j = 0; j < 64; j += 4) {
            float yv[4];
            #pragma unroll
            for (int q = 0; q < 4; ++q) {
                int col = cb + j + q;
                float dot = __uint_as_float(d[j + q]);
                float num = fmaf(two_rc * dot, chb[col], -onep * shb[col]);
                float a = g2s[col] * asinhf(num * invd);
                float y = sinhf(a) * invrc;
                ysq = fmaf(y, y, ysq);
                yv[q] = y;
            }
            *(float4*)(orow + j) = make_float4(yv[0], yv[1], yv[2], yv[3]);
        }
    }
    g_ysq_part[(size_t)row * 4 + blockIdx.x] = ysq;

    TC_FENCE_BEFORE();
    __syncthreads();
    if (wid == 0) tc_dealloc(tmem, 512);

#else  // ------------- SIMT fallback (non-'a' PTX stage; never runs on GB300) -
    float (*As)[128] = (float(*)[128])(smem);
    float (*Bs)[128] = (float(*)[128])(smem + 16 * 128 * 4);

    const int tid = threadIdx.x;
    const int tx = tid & 15, ty = tid >> 4;
    const float cval = c_ptr[0];
    const float rc = sqrtf(cval);
    const float invrc = 1.0f / rc;

    for (int mh = 0; mh < 2; ++mh) {
        const int brow = blockIdx.y * MT + mh * 128;
        for (int nh = 0; nh < 2; ++nh) {
            const int bcol = blockIdx.x * NT + nh * 128;
            float acc[8][8];
            #pragma unroll
            for (int i = 0; i < 8; ++i)
                #pragma unroll
                for (int j = 0; j < 8; ++j) acc[i][j] = 0.f;

            for (int kt = 0; kt < IN; kt += 16) {
                #pragma unroll
                for (int l = 0; l < 2; ++l) {
                    int idx = tid + l * 256;
                    int r = idx >> 2, c4 = (idx & 3) << 2;
                    float4 v = *(const float4*)(X + (size_t)(brow + r) * IN + kt + c4);
                    As[c4 + 0][r] = v.x; As[c4 + 1][r] = v.y;
                    As[c4 + 2][r] = v.z; As[c4 + 3][r] = v.w;
                }
                #pragma unroll
                for (int l = 0; l < 2; ++l) {
                    int idx = tid + l * 256;
                    int r = idx >> 5, c4 = (idx & 31) << 2;
                    *(float4*)(&Bs[r][c4]) =
                        *(const float4*)(W + (size_t)(kt + r) * OUT + bcol + c4);
                }
                __syncthreads();
                #pragma unroll
                for (int k = 0; k < 16; ++k) {
                    float a[8], b[8];
                    #pragma unroll
                    for (int q = 0; q < 8; ++q) a[q] = As[k][ty * 8 + q];
                    #pragma unroll
                    for (int q = 0; q < 8; ++q) b[q] = Bs[k][tx * 8 + q];
                    #pragma unroll
                    for (int i = 0; i < 8; ++i)
                        #pragma unroll
                        for (int j = 0; j < 8; ++j)
                            acc[i][j] = fmaf(a[i], b[j], acc[i][j]);
                }
                __syncthreads();
            }
            #pragma unroll
            for (int i = 0; i < 8; ++i) {
                int n = brow + ty * 8 + i;
                float cx2 = g_cx2[n];
                float invd = 1.0f / fmaxf(1.0f - cx2, 1e-15f);
                float onep = 1.0f + cx2;
                float y[8];
                float ysq = 0.f;
                #pragma unroll
                for (int j = 0; j < 8; ++j) {
                    int o = bcol + tx * 8 + j;
                    float num = 2.0f * rc * acc[i][j] * g_colscale[o] * g_coshb[o]
                                - onep * g_sinhb[o];
                    float a = 2.0f * wgp[o] * asinhf(num * invd);
                    y[j] = sinhf(a) * invrc;
                    ysq = fmaf(y[j], y[j], ysq);
                }
                atomicAdd(&g_ysq_part[(size_t)n * 4 + blockIdx.x], ysq);
                float* orow = out + (size_t)n * OUT + bcol + tx * 8;
                *(float4*)(orow)     = make_float4(y[0], y[1], y[2], y[3]);
                *(float4*)(orow + 4) = make_float4(y[4], y[5], y[6], y[7]);
            }
            __syncthreads();
        }
    }
#endif
}

// ---------------- rescale: gyro-half map + ball projection -------------------
__global__ void rescale_kernel(float* __restrict__ out,
                               const float* __restrict__ c_ptr, int OUT) {
    int row = blockIdx.x;
    float tot = g_ysq_part[(size_t)row * 4 + 0] + g_ysq_part[(size_t)row * 4 + 1]
              + g_ysq_part[(size_t)row * 4 + 2] + g_ysq_part[(size_t)row * 4 + 3];
    float c = c_ptr[0];
    float denom = 1.0f + sqrtf(1.0f + c * tot);
    float scale = 1.0f / denom;
    float norm = fmaxf(sqrtf(tot) * scale, 1e-15f);
    float kk = -c;
    float maxnorm = (1.0f - 0.004f) * rsqrtf(fmaxf(fabsf(kk), 1e-15f));
    if (!(kk < 0.f)) maxnorm = 1e15f;
    if (norm > maxnorm) scale *= maxnorm / norm;

    float4* yr = (float4*)(out + (size_t)row * OUT);
    int n4 = OUT >> 2;
    for (int i = threadIdx.x; i < n4; i += blockDim.x) {
        float4 v = yr[i];
        v.x *= scale; v.y *= scale; v.z *= scale; v.w *= scale;
        yr[i] = v;
    }
}

// ---------------------------------------------------------------------------
extern "C" void kernel_launch(void* const* d_in, const int* in_sizes, int n_in,
                              void* d_out, int out_size) {
    const float* x    = (const float*)d_in[0];
    const float* w    = (const float*)d_in[1];
    const float* wg   = (const float*)d_in[2];
    const float* bias = (const float*)d_in[3];
    const float* c    = (const float*)d_in[4];
    float* out = (float*)d_out;

    int OUT = in_sizes[2];
    int IN  = in_sizes[1] / OUT;
    int N   = in_sizes[0] / IN;

    static int smem_set = 0;
    if (!smem_set) {
        cudaFuncSetAttribute(gemm_tc_kernel, cudaFuncAttributeMaxDynamicSharedMemorySize,
                             SMEM_BYTES);
        smem_set = 1;
    }

    prep_kernel<<<(OUT + 255) / 256, 256>>>(w, bias, c, IN, OUT);
    convert_w_kernel<<<dim3(OUT / 32, IN / 32), dim3(32, 32)>>>(w, IN, OUT);
    convert_x_kernel<<<N, 256>>>(x, c, IN);
    dim3 grid(OUT / NT, N / MT);
    gemm_tc_kernel<<<grid, 256, SMEM_BYTES>>>(x, w, wg, c, out, N, IN, OUT);
    rescale_kernel<<<N, 256>>>(out, c, OUT);
}

// round 6
// speedup vs baseline: 1.5511x; 1.5511x over previous
#include <cuda_runtime.h>
#include <cuda_bf16.h>
#include <math.h>
#include <stdint.h>

// ---------------------------------------------------------------------------
// PoincareLinear via tcgen05 bf16 split GEMM (sm_103a) + SIMT fallback body
// for the non-'a' PTX stage.
//   dot = x_hi@w_hi + x_hi@w_lo + x_lo@w_hi   (K_eff = 3*1024)
//   256x256 tile/CTA, 3-stage cp.async pipeline with prefetch distance 2.
//   Epilogue: MUFU-based sinh(g*asinh(u)) + per-row ||y||^2 partials.
// ---------------------------------------------------------------------------

#if defined(__CUDA_ARCH_FEAT_SM103_ALL) || defined(__CUDA_ARCH_FEAT_SM100_ALL) || \
    defined(__CUDA_ARCH_SPECIFIC__) || defined(__CUDA_ARCH_FAMILY_SPECIFIC__)
#define HAS_TCGEN05 1
#else
#define HAS_TCGEN05 0
#endif

#define N_MAX   32768
#define IN_MAX  1024
#define OUT_MAX 1024

__device__ __nv_bfloat16 g_xhi[(size_t)N_MAX * IN_MAX];
__device__ __nv_bfloat16 g_xlo[(size_t)N_MAX * IN_MAX];
__device__ __nv_bfloat16 g_whi[(size_t)OUT_MAX * IN_MAX];   // [out][in], colscale folded
__device__ __nv_bfloat16 g_wlo[(size_t)OUT_MAX * IN_MAX];
__device__ float g_colscale[OUT_MAX];
__device__ float g_coshb[OUT_MAX];
__device__ float g_sinhb[OUT_MAX];
__device__ float g_cx2[N_MAX];
__device__ float g_ysq_part[(size_t)N_MAX * 4];   // per-row, per-col-CTA partial ||y||^2

constexpr uint64_t kSmemDescBaseSW128 =
    (uint64_t(2) << 61) | (uint64_t(1) << 46) | (uint64_t(64) << 32) | (uint64_t(1) << 16);

// ---------------- generic helpers -------------------------------------------
__device__ __forceinline__ uint32_t smem_u32(const void* p) {
    uint32_t a;
    asm("{ .reg .u64 t; cvta.to.shared.u64 t, %1; cvt.u32.u64 %0, t; }"
        : "=r"(a) : "l"(p));
    return a;
}
#define SW128(off) ((off) ^ (((off) >> 3) & 0x70))

__device__ __forceinline__ float block_reduce_sum(float v) {
    __shared__ float red[32];
    int lane = threadIdx.x & 31, wid = threadIdx.x >> 5;
    #pragma unroll
    for (int o = 16; o > 0; o >>= 1) v += __shfl_down_sync(0xffffffff, v, o);
    if (lane == 0) red[wid] = v;
    __syncthreads();
    int nw = (blockDim.x + 31) >> 5;
    v = (threadIdx.x < nw) ? red[threadIdx.x] : 0.f;
    if (wid == 0)
        #pragma unroll
        for (int o = 16; o > 0; o >>= 1) v += __shfl_down_sync(0xffffffff, v, o);
    return v;
}

#if HAS_TCGEN05
// ---------------- tcgen05 / mbarrier / cp.async wrappers ---------------------
__device__ __forceinline__ uint32_t elect_one() {
    uint32_t p;
    asm volatile("{ .reg .pred p; elect.sync _|p, 0xFFFFFFFF; selp.b32 %0,1,0,p; }"
                 : "=r"(p));
    return p;
}
__device__ __forceinline__ uint64_t make_desc(uint32_t addr) {
    return kSmemDescBaseSW128 | ((uint64_t)(addr >> 4) & 0x3FFF);
}
__device__ __forceinline__ void mbar_init(uint32_t a, uint32_t cnt) {
    asm volatile("mbarrier.init.shared.b64 [%0], %1;" :: "r"(a), "r"(cnt) : "memory");
}
__device__ __forceinline__ void mbar_wait(uint32_t a, uint32_t parity) {
    uint32_t done;
    asm volatile("{ .reg .pred p; mbarrier.try_wait.parity.acquire.cta.shared::cta.b64 p, [%1], %2;"
                 " selp.b32 %0,1,0,p; }" : "=r"(done) : "r"(a), "r"(parity) : "memory");
    if (!done) {
        asm volatile("{ .reg .pred P1; WL%=:"
                     " mbarrier.try_wait.parity.acquire.cta.shared::cta.b64 P1, [%0], %1, 0x989680;"
                     " @P1 bra.uni WD%=; bra.uni WL%=; WD%=: }"
                     :: "r"(a), "r"(parity) : "memory");
    }
}
__device__ __forceinline__ void tc_alloc(uint32_t smem_dst, uint32_t ncols) {
    asm volatile("tcgen05.alloc.cta_group::1.sync.aligned.shared::cta.b32 [%0], %1;"
                 :: "r"(smem_dst), "r"(ncols) : "memory");
}
__device__ __forceinline__ void tc_dealloc(uint32_t tmem, uint32_t ncols) {
    asm volatile("tcgen05.dealloc.cta_group::1.sync.aligned.b32 %0, %1;" :: "r"(tmem), "r"(ncols));
}
__device__ __forceinline__ void tc_relinquish() {
    asm volatile("tcgen05.relinquish_alloc_permit.cta_group::1.sync.aligned;");
}
__device__ __forceinline__ void tc_commit(uint32_t mbar) {
    asm volatile("tcgen05.commit.cta_group::1.mbarrier::arrive::one.shared::cluster.b64 [%0];"
                 :: "r"(mbar) : "memory");
}
__device__ __forceinline__ void mma_f16_ss(uint32_t d, uint64_t ad, uint64_t bd,
                                           uint32_t idesc, bool acc) {
    uint32_t en = acc ? 1u : 0u;
    asm volatile("{ .reg .pred p; setp.ne.u32 p, %4, 0;"
                 " tcgen05.mma.cta_group::1.kind::f16 [%0], %1, %2, %3, {%5,%5,%5,%5}, p; }"
                 :: "r"(d), "l"(ad), "l"(bd), "r"(idesc), "r"(en), "r"(0u) : "memory");
}
__device__ __forceinline__ void cp16(uint32_t dst, const void* src) {
    asm volatile("cp.async.cg.shared.global [%0], [%1], 16;" :: "r"(dst), "l"(src));
}
#define CP_COMMIT() asm volatile("cp.async.commit_group;" ::: "memory")
#define CP_WAIT1()  asm volatile("cp.async.wait_group 1;" ::: "memory")
#define TC_LD_X32(r, addr) \
    asm volatile("tcgen05.ld.sync.aligned.32x32b.x32.b32 " \
        "{%0,%1,%2,%3,%4,%5,%6,%7,%8,%9,%10,%11,%12,%13,%14,%15," \
        "%16,%17,%18,%19,%20,%21,%22,%23,%24,%25,%26,%27,%28,%29,%30,%31}, [%32];" \
        : "=r"((r)[0]),"=r"((r)[1]),"=r"((r)[2]),"=r"((r)[3]),"=r"((r)[4]),"=r"((r)[5]), \
          "=r"((r)[6]),"=r"((r)[7]),"=r"((r)[8]),"=r"((r)[9]),"=r"((r)[10]),"=r"((r)[11]), \
          "=r"((r)[12]),"=r"((r)[13]),"=r"((r)[14]),"=r"((r)[15]),"=r"((r)[16]),"=r"((r)[17]), \
          "=r"((r)[18]),"=r"((r)[19]),"=r"((r)[20]),"=r"((r)[21]),"=r"((r)[22]),"=r"((r)[23]), \
          "=r"((r)[24]),"=r"((r)[25]),"=r"((r)[26]),"=r"((r)[27]),"=r"((r)[28]),"=r"((r)[29]), \
          "=r"((r)[30]),"=r"((r)[31]) : "r"(addr))
#define TC_WAIT_LD()  asm volatile("tcgen05.wait::ld.sync.aligned;" ::: "memory")
#define TC_FENCE_AFTER()  asm volatile("tcgen05.fence::after_thread_sync;" ::: "memory")
#define TC_FENCE_BEFORE() asm volatile("tcgen05.fence::before_thread_sync;" ::: "memory")
#define FENCE_ASYNC_SHARED() asm volatile("fence.proxy.async.shared::cta;" ::: "memory")
#endif // HAS_TCGEN05

// ---------------- prep: colscale + cosh/sinh(2 rc b), block per column -------
__global__ void prep_kernel(const float* __restrict__ w, const float* __restrict__ bias,
                            const float* __restrict__ c_ptr, int IN, int OUT) {
    int o = blockIdx.x;
    float s = 0.f;
    for (int i = threadIdx.x; i < IN; i += blockDim.x) {
        float v = w[(size_t)i * OUT + o];
        s = fmaf(v, v, s);
    }
    float tot = block_reduce_sum(s);
    if (threadIdx.x == 0) {
        g_colscale[o] = 1.0f / fmaxf(sqrtf(tot), 1e-15f);
        float rc = sqrtf(c_ptr[0]);
        float d = 2.0f * rc * bias[o];
        g_coshb[o] = coshf(d);
        g_sinhb[o] = sinhf(d);
    }
}

// ---------------- transpose + scale + bf16 split of w ------------------------
__global__ void convert_w_kernel(const float* __restrict__ w, int IN, int OUT) {
    __shared__ float t[32][33];
    int n0 = blockIdx.x * 32, k0 = blockIdx.y * 32;
    int tx = threadIdx.x, ty = threadIdx.y;
    t[ty][tx] = w[(size_t)(k0 + ty) * OUT + n0 + tx];
    __syncthreads();
    int n = n0 + ty, k = k0 + tx;
    float v = t[tx][ty] * g_colscale[n];
    __nv_bfloat16 hi = __float2bfloat16(v);
    float r = v - __bfloat162float(hi);
    g_whi[(size_t)n * IN + k] = hi;
    g_wlo[(size_t)n * IN + k] = __float2bfloat16(r);
}

// ---------------- x -> bf16 hi/lo, fused cx2 ---------------------------------
__global__ void convert_x_kernel(const float* __restrict__ x,
                                 const float* __restrict__ c_ptr, int IN) {
    int row = blockIdx.x;
    if (threadIdx.x < 4) g_ysq_part[(size_t)row * 4 + threadIdx.x] = 0.f;
    const float4* xr = (const float4*)(x + (size_t)row * IN);
    int n4 = IN >> 2;
    float s = 0.f;
    for (int i = threadIdx.x; i < n4; i += blockDim.x) {
        float4 v = xr[i];
        s = fmaf(v.x, v.x, s); s = fmaf(v.y, v.y, s);
        s = fmaf(v.z, v.z, s); s = fmaf(v.w, v.w, s);
        __nv_bfloat16 h0 = __float2bfloat16(v.x), h1 = __float2bfloat16(v.y);
        __nv_bfloat16 h2 = __float2bfloat16(v.z), h3 = __float2bfloat16(v.w);
        __nv_bfloat16 l0 = __float2bfloat16(v.x - __bfloat162float(h0));
        __nv_bfloat16 l1 = __float2bfloat16(v.y - __bfloat162float(h1));
        __nv_bfloat16 l2 = __float2bfloat16(v.z - __bfloat162float(h2));
        __nv_bfloat16 l3 = __float2bfloat16(v.w - __bfloat162float(h3));
        uint2 hp, lp;
        hp.x = ((uint32_t)__bfloat16_as_ushort(h1) << 16) | __bfloat16_as_ushort(h0);
        hp.y = ((uint32_t)__bfloat16_as_ushort(h3) << 16) | __bfloat16_as_ushort(h2);
        lp.x = ((uint32_t)__bfloat16_as_ushort(l1) << 16) | __bfloat16_as_ushort(l0);
        lp.y = ((uint32_t)__bfloat16_as_ushort(l3) << 16) | __bfloat16_as_ushort(l2);
        *(uint2*)(g_xhi + (size_t)row * IN + i * 4) = hp;
        *(uint2*)(g_xlo + (size_t)row * IN + i * 4) = lp;
    }
    float tot = block_reduce_sum(s);
    if (threadIdx.x == 0) g_cx2[row] = c_ptr[0] * tot;
}

// ---------------- GEMM + fused Poincare epilogue -----------------------------
#define MT 256
#define NT 256
#define KC 64
// per-dispatch M = 128
#define IDESC ((1u<<4) | (1u<<7) | (1u<<10) | ((NT/8u)<<17) | (8u<<24))

#define OFF_TMEM 0u
#define OFF_MB   8u                         // 3 mbarriers at 8,16,24
#define OFF_PAR  64u                        // 3 * NT floats = 3072 B
#define OFF_T    4096u
#define ASZ      (MT * 128u)                // 32 KB
#define BSZ      (NT * 128u)                // 32 KB
#define STAGE    (ASZ + BSZ)                // 64 KB
#define NSTAGE   3
#define SMEM_BYTES (OFF_T + NSTAGE * STAGE) // 200704

__global__ __launch_bounds__(256, 1)
void gemm_tc_kernel(const float* __restrict__ X, const float* __restrict__ W,
                    const float* __restrict__ wgp, const float* __restrict__ c_ptr,
                    float* __restrict__ out, int Nrows, int IN, int OUT) {
    extern __shared__ char smem[];
#if HAS_TCGEN05
    const uint32_t sb = smem_u32(smem);
    const int tid = threadIdx.x;
    const int wid = tid >> 5, lane = tid & 31;
    const int brow = blockIdx.y * MT, bcol = blockIdx.x * NT;
    const int nchunk = (3 * IN) / KC;   // 48

    if (wid == 0) { tc_alloc(sb + OFF_TMEM, 512); tc_relinquish(); }
    if (tid == 0) {
        mbar_init(sb + OFF_MB + 0, 1);
        mbar_init(sb + OFF_MB + 8, 1);
        mbar_init(sb + OFF_MB + 16, 1);
    }
    float* chb = (float*)(smem + OFF_PAR);
    float* shb = chb + NT;
    float* g2s = shb + NT;
    if (tid < NT) {
        int o = bcol + tid;
        chb[tid] = g_coshb[o];
        shb[tid] = g_sinhb[o];
        g2s[tid] = 2.0f * wgp[o];
    }
    __syncthreads();
    uint32_t tmem;
    asm volatile("ld.shared.b32 %0, [%1];" : "=r"(tmem) : "r"(sb + OFF_TMEM));

    // per-chunk segment select: 0..15 hi*hi, 16..31 hi*lo, 32..47 lo*hi
    auto issue_loads = [&](int c, int s) {
        const int seg = c >> 4;
        const int k0  = (c & 15) * KC;
        const __nv_bfloat16* srcA = (seg == 2) ? g_xlo : g_xhi;
        const __nv_bfloat16* srcB = (seg == 1) ? g_wlo : g_whi;
        const uint32_t Aoff = OFF_T + (uint32_t)s * STAGE;
        const uint32_t Boff = Aoff + ASZ;
        #pragma unroll
        for (int l = 0; l < 8; ++l) {
            int idx = tid + l * 256;            // 0..2047
            int r = idx >> 3, j = idx & 7;
            cp16(sb + Aoff + SW128((uint32_t)(r * 128 + j * 16)),
                 srcA + (size_t)(brow + r) * IN + k0 + j * 8);
        }
        #pragma unroll
        for (int l = 0; l < 8; ++l) {
            int idx = tid + l * 256;
            int r = idx >> 3, j = idx & 7;
            cp16(sb + Boff + SW128((uint32_t)(r * 128 + j * 16)),
                 srcB + (size_t)(bcol + r) * IN + k0 + j * 8);
        }
    };

    // prologue: stages 0,1 <- chunks 0,1 (prefetch distance 2, 3 buffers)
    issue_loads(0, 0); CP_COMMIT();
    issue_loads(1, 1); CP_COMMIT();

    for (int c = 0; c < nchunk; ++c) {
        const int s = c % 3;
        CP_WAIT1();                 // chunk c resident (its group + at most 1 newer pending)
        FENCE_ASYNC_SHARED();
        __syncthreads();
        if (wid == 0 && elect_one()) {
            const uint32_t Aoff = OFF_T + (uint32_t)s * STAGE;
            uint64_t ad = make_desc(sb + Aoff);
            uint64_t bd = make_desc(sb + Aoff + ASZ);
            #pragma unroll
            for (int k = 0; k < 4; ++k) {
                bool acc = (c > 0) || (k > 0);
                mma_f16_ss(tmem,       ad + k * 2,        bd + k * 2, IDESC, acc);
                mma_f16_ss(tmem + 256, ad + 1024 + k * 2, bd + k * 2, IDESC, acc);
            }
            tc_commit(sb + OFF_MB + 8u * (uint32_t)s);
        }
        if (c + 2 < nchunk) {
            const int s2 = (c + 2) % 3;     // == (c-1) % 3
            if (c >= 1) {
                // stage s2 previously held chunk c-1; wait its MMAs drained
                mbar_wait(sb + OFF_MB + 8u * (uint32_t)s2,
                          (uint32_t)(((c - 1) / 3) & 1));
            }
            issue_loads(c + 2, s2);
        }
        CP_COMMIT();                // exactly one group per iteration (may be empty)
    }
    // final: wait last commit on each stage (commit index nchunk/3 - 1)
    {
        uint32_t fp = (uint32_t)(((nchunk / 3) - 1) & 1);
        mbar_wait(sb + OFF_MB + 0, fp);
        mbar_wait(sb + OFF_MB + 8, fp);
        mbar_wait(sb + OFF_MB + 16, fp);
    }
    TC_FENCE_AFTER();

    // ---- epilogue: 8 warps; half = wid>>2 selects M-half / TMEM 256-col bank
    const float rc = sqrtf(c_ptr[0]);
    const float invrc = 1.0f / rc;
    const int half = wid >> 2, sub = wid & 3;
    const int row = brow + half * 128 + sub * 32 + lane;
    const float cx2 = g_cx2[row];
    const float invd = 1.0f / fmaxf(1.0f - cx2, 1e-15f);
    const float onep = 1.0f + cx2;
    const float two_rc = 2.0f * rc;
    float ysq = 0.f;

    #pragma unroll
    for (int cc = 0; cc < 4; ++cc) {
        const int cb = cc * 64;
        uint32_t d[64];
        TC_LD_X32(d, tmem + half * 256 + cb);
        TC_LD_X32(d + 32, tmem + half * 256 + cb + 32);
        TC_WAIT_LD();
        float* orow = out + (size_t)row * OUT + bcol + cb;
        #pragma unroll
        for (int j = 0; j < 64; j += 4) {
            float yv[4];
            #pragma unroll
            for (int q = 0; q < 4; ++q) {
                int col = cb + j + q;
                float dot = __uint_as_float(d[j + q]);
                float num = fmaf(two_rc * dot, chb[col], -onep * shb[col]);
                float u = num * invd;
                // sinh(g*asinh(u)) = sign(u) * (t^g - t^-g)/2,  t = sqrt(u^2+1)+|u|
                float sq = sqrtf(fmaf(u, u, 1.0f));
                float t  = sq + fabsf(u);
                float lt = __logf(t);
                float p  = __expf(g2s[col] * lt);
                float mag = (p - __fdividef(1.0f, p)) * 0.5f * invrc;
                float y = copysignf(mag, u);
                ysq = fmaf(y, y, ysq);
                yv[q] = y;
            }
            *(float4*)(orow + j) = make_float4(yv[0], yv[1], yv[2], yv[3]);
        }
    }
    g_ysq_part[(size_t)row * 4 + blockIdx.x] = ysq;

    TC_FENCE_BEFORE();
    __syncthreads();
    if (wid == 0) tc_dealloc(tmem, 512);

#else  // ------------- SIMT fallback (non-'a' PTX stage; never runs on GB300) -
    float (*As)[128] = (float(*)[128])(smem);
    float (*Bs)[128] = (float(*)[128])(smem + 16 * 128 * 4);

    const int tid = threadIdx.x;
    const int tx = tid & 15, ty = tid >> 4;
    const float cval = c_ptr[0];
    const float rc = sqrtf(cval);
    const float invrc = 1.0f / rc;

    for (int mh = 0; mh < 2; ++mh) {
        const int brow = blockIdx.y * MT + mh * 128;
        for (int nh = 0; nh < 2; ++nh) {
            const int bcol = blockIdx.x * NT + nh * 128;
            float acc[8][8];
            #pragma unroll
            for (int i = 0; i < 8; ++i)
                #pragma unroll
                for (int j = 0; j < 8; ++j) acc[i][j] = 0.f;

            for (int kt = 0; kt < IN; kt += 16) {
                #pragma unroll
                for (int l = 0; l < 2; ++l) {
                    int idx = tid + l * 256;
                    int r = idx >> 2, c4 = (idx & 3) << 2;
                    float4 v = *(const float4*)(X + (size_t)(brow + r) * IN + kt + c4);
                    As[c4 + 0][r] = v.x; As[c4 + 1][r] = v.y;
                    As[c4 + 2][r] = v.z; As[c4 + 3][r] = v.w;
                }
                #pragma unroll
                for (int l = 0; l < 2; ++l) {
                    int idx = tid + l * 256;
                    int r = idx >> 5, c4 = (idx & 31) << 2;
                    *(float4*)(&Bs[r][c4]) =
                        *(const float4*)(W + (size_t)(kt + r) * OUT + bcol + c4);
                }
                __syncthreads();
                #pragma unroll
                for (int k = 0; k < 16; ++k) {
                    float a[8], b[8];
                    #pragma unroll
                    for (int q = 0; q < 8; ++q) a[q] = As[k][ty * 8 + q];
                    #pragma unroll
                    for (int q = 0; q < 8; ++q) b[q] = Bs[k][tx * 8 + q];
                    #pragma unroll
                    for (int i = 0; i < 8; ++i)
                        #pragma unroll
                        for (int j = 0; j < 8; ++j)
                            acc[i][j] = fmaf(a[i], b[j], acc[i][j]);
                }
                __syncthreads();
            }
            #pragma unroll
            for (int i = 0; i < 8; ++i) {
                int n = brow + ty * 8 + i;
                float cx2 = g_cx2[n];
                float invd = 1.0f / fmaxf(1.0f - cx2, 1e-15f);
                float onep = 1.0f + cx2;
                float y[8];
                float ysq = 0.f;
                #pragma unroll
                for (int j = 0; j < 8; ++j) {
                    int o = bcol + tx * 8 + j;
                    float num = 2.0f * rc * acc[i][j] * g_colscale[o] * g_coshb[o]
                                - onep * g_sinhb[o];
                    float a = 2.0f * wgp[o] * asinhf(num * invd);
                    y[j] = sinhf(a) * invrc;
                    ysq = fmaf(y[j], y[j], ysq);
                }
                atomicAdd(&g_ysq_part[(size_t)n * 4 + blockIdx.x], ysq);
                float* orow = out + (size_t)n * OUT + bcol + tx * 8;
                *(float4*)(orow)     = make_float4(y[0], y[1], y[2], y[3]);
                *(float4*)(orow + 4) = make_float4(y[4], y[5], y[6], y[7]);
            }
            __syncthreads();
        }
    }
#endif
}

// ---------------- rescale: gyro-half map + ball projection -------------------
__global__ void rescale_kernel(float* __restrict__ out,
                               const float* __restrict__ c_ptr, int OUT) {
    int row = blockIdx.x;
    float tot = g_ysq_part[(size_t)row * 4 + 0] + g_ysq_part[(size_t)row * 4 + 1]
              + g_ysq_part[(size_t)row * 4 + 2] + g_ysq_part[(size_t)row * 4 + 3];
    float c = c_ptr[0];
    float denom = 1.0f + sqrtf(1.0f + c * tot);
    float scale = 1.0f / denom;
    float norm = fmaxf(sqrtf(tot) * scale, 1e-15f);
    float kk = -c;
    float maxnorm = (1.0f - 0.004f) * rsqrtf(fmaxf(fabsf(kk), 1e-15f));
    if (!(kk < 0.f)) maxnorm = 1e15f;
    if (norm > maxnorm) scale *= maxnorm / norm;

    float4* yr = (float4*)(out + (size_t)row * OUT);
    int n4 = OUT >> 2;
    for (int i = threadIdx.x; i < n4; i += blockDim.x) {
        float4 v = yr[i];
        v.x *= scale; v.y *= scale; v.z *= scale; v.w *= scale;
        yr[i] = v;
    }
}

// ---------------------------------------------------------------------------
extern "C" void kernel_launch(void* const* d_in, const int* in_sizes, int n_in,
                              void* d_out, int out_size) {
    const float* x    = (const float*)d_in[0];
    const float* w    = (const float*)d_in[1];
    const float* wg   = (const float*)d_in[2];
    const float* bias = (const float*)d_in[3];
    const float* c    = (const float*)d_in[4];
    float* out = (float*)d_out;

    int OUT = in_sizes[2];
    int IN  = in_sizes[1] / OUT;
    int N   = in_sizes[0] / IN;

    static int smem_set = 0;
    if (!smem_set) {
        cudaFuncSetAttribute(gemm_tc_kernel, cudaFuncAttributeMaxDynamicSharedMemorySize,
                             SMEM_BYTES);
        smem_set = 1;
    }

    prep_kernel<<<OUT, 256>>>(w, bias, c, IN, OUT);
    convert_w_kernel<<<dim3(OUT / 32, IN / 32), dim3(32, 32)>>>(w, IN, OUT);
    convert_x_kernel<<<N, 256>>>(x, c, IN);
    dim3 grid(OUT / NT, N / MT);
    gemm_tc_kernel<<<grid, 256, SMEM_BYTES>>>(x, w, wg, c, out, N, IN, OUT);
    rescale_kernel<<<N, 256>>>(out, c, OUT);
}

// round 7
// speedup vs baseline: 1.5926x; 1.0268x over previous
#include <cuda_runtime.h>
#include <cuda_bf16.h>
#include <math.h>
#include <stdint.h>

// ---------------------------------------------------------------------------
// PoincareLinear via tcgen05 bf16 split GEMM (sm_103a) + SIMT fallback body.
//   dot = x_hi@w_hi + x_hi@w_lo + x_lo@w_hi   (K_eff = 3*1024)
//   Tiles stored PRE-SWIZZLED in tile-major global layout so the GEMM loads
//   each 32KB tile with ONE cp.async.bulk (mbarrier complete_tx pipeline,
//   3 stages, prefetch distance 2, single control thread).
// ---------------------------------------------------------------------------

#if defined(__CUDA_ARCH_FEAT_SM103_ALL) || defined(__CUDA_ARCH_FEAT_SM100_ALL) || \
    defined(__CUDA_ARCH_SPECIFIC__) || defined(__CUDA_ARCH_FAMILY_SPECIFIC__)
#define HAS_TCGEN05 1
#else
#define HAS_TCGEN05 0
#endif

#define N_MAX   32768
#define IN_MAX  1024
#define OUT_MAX 1024
#define TILE_BYTES 32768u            // 256 rows x 128 B

// tile-major, pre-swizzled: blob[(rowblock*16 + kchunk)*32KB + SW128(r*128+j*16)]
__device__ uint8_t g_xhi_t[(size_t)N_MAX * IN_MAX * 2];
__device__ uint8_t g_xlo_t[(size_t)N_MAX * IN_MAX * 2];
__device__ uint8_t g_whi_t[(size_t)OUT_MAX * IN_MAX * 2];
__device__ uint8_t g_wlo_t[(size_t)OUT_MAX * IN_MAX * 2];
__device__ float g_colscale[OUT_MAX];
__device__ float g_coshb[OUT_MAX];
__device__ float g_sinhb[OUT_MAX];
__device__ float g_cx2[N_MAX];
__device__ float g_ysq_part[(size_t)N_MAX * 4];

constexpr uint64_t kSmemDescBaseSW128 =
    (uint64_t(2) << 61) | (uint64_t(1) << 46) | (uint64_t(64) << 32) | (uint64_t(1) << 16);

// ---------------- generic helpers -------------------------------------------
__device__ __forceinline__ uint32_t smem_u32(const void* p) {
    uint32_t a;
    asm("{ .reg .u64 t; cvta.to.shared.u64 t, %1; cvt.u32.u64 %0, t; }"
        : "=r"(a) : "l"(p));
    return a;
}
#define SW128(off) ((off) ^ (((off) >> 3) & 0x70))

__device__ __forceinline__ float block_reduce_sum(float v) {
    __shared__ float red[32];
    int lane = threadIdx.x & 31, wid = threadIdx.x >> 5;
    #pragma unroll
    for (int o = 16; o > 0; o >>= 1) v += __shfl_down_sync(0xffffffff, v, o);
    if (lane == 0) red[wid] = v;
    __syncthreads();
    int nw = (blockDim.x + 31) >> 5;
    v = (threadIdx.x < nw) ? red[threadIdx.x] : 0.f;
    if (wid == 0)
        #pragma unroll
        for (int o = 16; o > 0; o >>= 1) v += __shfl_down_sync(0xffffffff, v, o);
    return v;
}

__device__ __forceinline__ uint32_t pack_bf16x2(float a, float b) {
    __nv_bfloat16 ha = __float2bfloat16(a), hb = __float2bfloat16(b);
    return ((uint32_t)__bfloat16_as_ushort(hb) << 16) | __bfloat16_as_ushort(ha);
}

#if HAS_TCGEN05
// ---------------- tcgen05 / mbarrier / bulk-copy wrappers --------------------
__device__ __forceinline__ uint32_t elect_one() {
    uint32_t p;
    asm volatile("{ .reg .pred p; elect.sync _|p, 0xFFFFFFFF; selp.b32 %0,1,0,p; }"
                 : "=r"(p));
    return p;
}
__device__ __forceinline__ uint64_t make_desc(uint32_t addr) {
    return kSmemDescBaseSW128 | ((uint64_t)(addr >> 4) & 0x3FFF);
}
__device__ __forceinline__ void mbar_init(uint32_t a, uint32_t cnt) {
    asm volatile("mbarrier.init.shared.b64 [%0], %1;" :: "r"(a), "r"(cnt) : "memory");
}
__device__ __forceinline__ void mbar_expect_tx(uint32_t a, uint32_t bytes) {
    asm volatile("mbarrier.arrive.expect_tx.shared.b64 _, [%0], %1;"
                 :: "r"(a), "r"(bytes) : "memory");
}
__device__ __forceinline__ void mbar_wait(uint32_t a, uint32_t parity) {
    uint32_t done;
    asm volatile("{ .reg .pred p; mbarrier.try_wait.parity.acquire.cta.shared::cta.b64 p, [%1], %2;"
                 " selp.b32 %0,1,0,p; }" : "=r"(done) : "r"(a), "r"(parity) : "memory");
    if (!done) {
        asm volatile("{ .reg .pred P1; WL%=:"
                     " mbarrier.try_wait.parity.acquire.cta.shared::cta.b64 P1, [%0], %1, 0x989680;"
                     " @P1 bra.uni WD%=; bra.uni WL%=; WD%=: }"
                     :: "r"(a), "r"(parity) : "memory");
    }
}
__device__ __forceinline__ void bulk_g2s(uint32_t dst, const void* src, uint32_t bytes,
                                         uint32_t mbar) {
    asm volatile("cp.async.bulk.shared::cta.global.mbarrier::complete_tx::bytes"
                 " [%0], [%1], %2, [%3];"
                 :: "r"(dst), "l"(src), "r"(bytes), "r"(mbar) : "memory");
}
__device__ __forceinline__ void tc_alloc(uint32_t smem_dst, uint32_t ncols) {
    asm volatile("tcgen05.alloc.cta_group::1.sync.aligned.shared::cta.b32 [%0], %1;"
                 :: "r"(smem_dst), "r"(ncols) : "memory");
}
__device__ __forceinline__ void tc_dealloc(uint32_t tmem, uint32_t ncols) {
    asm volatile("tcgen05.dealloc.cta_group::1.sync.aligned.b32 %0, %1;" :: "r"(tmem), "r"(ncols));
}
__device__ __forceinline__ void tc_relinquish() {
    asm volatile("tcgen05.relinquish_alloc_permit.cta_group::1.sync.aligned;");
}
__device__ __forceinline__ void tc_commit(uint32_t mbar) {
    asm volatile("tcgen05.commit.cta_group::1.mbarrier::arrive::one.shared::cluster.b64 [%0];"
                 :: "r"(mbar) : "memory");
}
__device__ __forceinline__ void mma_f16_ss(uint32_t d, uint64_t ad, uint64_t bd,
                                           uint32_t idesc, bool acc) {
    uint32_t en = acc ? 1u : 0u;
    asm volatile("{ .reg .pred p; setp.ne.u32 p, %4, 0;"
                 " tcgen05.mma.cta_group::1.kind::f16 [%0], %1, %2, %3, {%5,%5,%5,%5}, p; }"
                 :: "r"(d), "l"(ad), "l"(bd), "r"(idesc), "r"(en), "r"(0u) : "memory");
}
#define TC_LD_X32(r, addr) \
    asm volatile("tcgen05.ld.sync.aligned.32x32b.x32.b32 " \
        "{%0,%1,%2,%3,%4,%5,%6,%7,%8,%9,%10,%11,%12,%13,%14,%15," \
        "%16,%17,%18,%19,%20,%21,%22,%23,%24,%25,%26,%27,%28,%29,%30,%31}, [%32];" \
        : "=r"((r)[0]),"=r"((r)[1]),"=r"((r)[2]),"=r"((r)[3]),"=r"((r)[4]),"=r"((r)[5]), \
          "=r"((r)[6]),"=r"((r)[7]),"=r"((r)[8]),"=r"((r)[9]),"=r"((r)[10]),"=r"((r)[11]), \
          "=r"((r)[12]),"=r"((r)[13]),"=r"((r)[14]),"=r"((r)[15]),"=r"((r)[16]),"=r"((r)[17]), \
          "=r"((r)[18]),"=r"((r)[19]),"=r"((r)[20]),"=r"((r)[21]),"=r"((r)[22]),"=r"((r)[23]), \
          "=r"((r)[24]),"=r"((r)[25]),"=r"((r)[26]),"=r"((r)[27]),"=r"((r)[28]),"=r"((r)[29]), \
          "=r"((r)[30]),"=r"((r)[31]) : "r"(addr))
#define TC_WAIT_LD()  asm volatile("tcgen05.wait::ld.sync.aligned;" ::: "memory")
#define TC_FENCE_AFTER()  asm volatile("tcgen05.fence::after_thread_sync;" ::: "memory")
#define TC_FENCE_BEFORE() asm volatile("tcgen05.fence::before_thread_sync;" ::: "memory")
#endif // HAS_TCGEN05

// ---------------- prep: colscale + cosh/sinh(2 rc b), block per column -------
__global__ void prep_kernel(const float* __restrict__ w, const float* __restrict__ bias,
                            const float* __restrict__ c_ptr, int IN, int OUT) {
    int o = blockIdx.x;
    float s = 0.f;
    for (int i = threadIdx.x; i < IN; i += blockDim.x) {
        float v = w[(size_t)i * OUT + o];
        s = fmaf(v, v, s);
    }
    float tot = block_reduce_sum(s);
    if (threadIdx.x == 0) {
        g_colscale[o] = 1.0f / fmaxf(sqrtf(tot), 1e-15f);
        float rc = sqrtf(c_ptr[0]);
        float d = 2.0f * rc * bias[o];
        g_coshb[o] = coshf(d);
        g_sinhb[o] = sinhf(d);
    }
}

// ---------------- w -> transposed, scaled, bf16 split, tile-major swizzled ---
__global__ void convert_w_kernel(const float* __restrict__ w, int IN, int OUT) {
    __shared__ float t[32][33];
    int n0 = blockIdx.x * 32, k0 = blockIdx.y * 32;
    int tx = threadIdx.x, ty = threadIdx.y;
    t[ty][tx] = w[(size_t)(k0 + ty) * OUT + n0 + tx];   // t[k_local][n_local]
    __syncthreads();
    if (tx < 4) {
        int n = n0 + ty;
        float cs = g_colscale[n];
        uint32_t hi4[4], lo4[4];
        #pragma unroll
        for (int p = 0; p < 4; ++p) {
            float a = t[tx * 8 + p * 2 + 0][ty] * cs;
            float b = t[tx * 8 + p * 2 + 1][ty] * cs;
            __nv_bfloat16 ha = __float2bfloat16(a), hb = __float2bfloat16(b);
            float ra = a - __bfloat162float(ha), rb = b - __bfloat162float(hb);
            hi4[p] = ((uint32_t)__bfloat16_as_ushort(hb) << 16) | __bfloat16_as_ushort(ha);
            lo4[p] = pack_bf16x2(ra, rb);
        }
        int k = k0 + tx * 8;
        int nb = n >> 8, kc = k >> 6, j = (k >> 3) & 7;
        size_t base = ((size_t)(nb * 16 + kc)) * TILE_BYTES
                    + SW128((uint32_t)((n & 255) * 128 + j * 16));
        *(uint4*)(g_whi_t + base) = make_uint4(hi4[0], hi4[1], hi4[2], hi4[3]);
        *(uint4*)(g_wlo_t + base) = make_uint4(lo4[0], lo4[1], lo4[2], lo4[3]);
    }
}

// ---------------- x -> bf16 hi/lo tile-major swizzled, fused cx2 -------------
__global__ void convert_x_kernel(const float* __restrict__ x,
                                 const float* __restrict__ c_ptr, int IN) {
    int row = blockIdx.x;
    int t = threadIdx.x;                 // 128 threads, 8 elements each
    if (t < 4) g_ysq_part[(size_t)row * 4 + t] = 0.f;
    const float4* xr = (const float4*)(x + (size_t)row * IN) + t * 2;
    float4 v0 = xr[0], v1 = xr[1];
    float s = v0.x*v0.x + v0.y*v0.y + v0.z*v0.z + v0.w*v0.w
            + v1.x*v1.x + v1.y*v1.y + v1.z*v1.z + v1.w*v1.w;
    float e[8] = {v0.x, v0.y, v0.z, v0.w, v1.x, v1.y, v1.z, v1.w};
    uint32_t hi4[4], lo4[4];
    #pragma unroll
    for (int p = 0; p < 4; ++p) {
        float a = e[p*2], b = e[p*2+1];
        __nv_bfloat16 ha = __float2bfloat16(a), hb = __float2bfloat16(b);
        float ra = a - __bfloat162float(ha), rb = b - __bfloat162float(hb);
        hi4[p] = ((uint32_t)__bfloat16_as_ushort(hb) << 16) | __bfloat16_as_ushort(ha);
        lo4[p] = pack_bf16x2(ra, rb);
    }
    int kc = t >> 3, j = t & 7;
    int rb = row >> 8, r = row & 255;
    size_t base = ((size_t)(rb * 16 + kc)) * TILE_BYTES
                + SW128((uint32_t)(r * 128 + j * 16));
    *(uint4*)(g_xhi_t + base) = make_uint4(hi4[0], hi4[1], hi4[2], hi4[3]);
    *(uint4*)(g_xlo_t + base) = make_uint4(lo4[0], lo4[1], lo4[2], lo4[3]);
    float tot = block_reduce_sum(s);
    if (threadIdx.x == 0) g_cx2[row] = c_ptr[0] * tot;
}

// ---------------- GEMM + fused Poincare epilogue -----------------------------
#define MT 256
#define NT 256
#define IDESC ((1u<<4) | (1u<<7) | (1u<<10) | ((NT/8u)<<17) | (8u<<24))

#define OFF_TMEM 0u
#define OFF_MBF  8u                         // full barriers: 8,16,24
#define OFF_MBE  32u                        // empty barriers: 32,40,48
#define OFF_PAR  64u                        // 3 * NT floats
#define OFF_T    4096u
#define ASZ      (MT * 128u)                // 32 KB
#define BSZ      (NT * 128u)                // 32 KB
#define STAGE    (ASZ + BSZ)                // 64 KB
#define SMEM_BYTES (OFF_T + 3u * STAGE)     // 200704

__global__ __launch_bounds__(256, 1)
void gemm_tc_kernel(const float* __restrict__ X, const float* __restrict__ W,
                    const float* __restrict__ wgp, const float* __restrict__ c_ptr,
                    float* __restrict__ out, int Nrows, int IN, int OUT) {
    extern __shared__ char smem[];
#if HAS_TCGEN05
    const uint32_t sb = smem_u32(smem);
    const int tid = threadIdx.x;
    const int wid = tid >> 5, lane = tid & 31;
    const int brow = blockIdx.y * MT, bcol = blockIdx.x * NT;
    const int nchunk = 48;

    if (wid == 0) { tc_alloc(sb + OFF_TMEM, 512); tc_relinquish(); }
    if (tid == 0) {
        #pragma unroll
        for (int s = 0; s < 3; ++s) {
            mbar_init(sb + OFF_MBF + 8u * s, 1);
            mbar_init(sb + OFF_MBE + 8u * s, 1);
        }
    }
    float* chb = (float*)(smem + OFF_PAR);
    float* shb = chb + NT;
    float* g2s = shb + NT;
    if (tid < NT) {
        int o = bcol + tid;
        chb[tid] = g_coshb[o];
        shb[tid] = g_sinhb[o];
        g2s[tid] = 2.0f * wgp[o];
    }
    __syncthreads();
    uint32_t tmem;
    asm volatile("ld.shared.b32 %0, [%1];" : "=r"(tmem) : "r"(sb + OFF_TMEM));

    if (tid == 0) {
        // chunk -> source blobs (tile-major, pre-swizzled)
        auto srcA = [&](int c) -> const uint8_t* {
            int seg = c >> 4, kc = c & 15;
            const uint8_t* p = (seg == 2) ? g_xlo_t : g_xhi_t;
            return p + ((size_t)(blockIdx.y * 16 + kc)) * TILE_BYTES;
        };
        auto srcB = [&](int c) -> const uint8_t* {
            int seg = c >> 4, kc = c & 15;
            const uint8_t* p = (seg == 1) ? g_wlo_t : g_whi_t;
            return p + ((size_t)(blockIdx.x * 16 + kc)) * TILE_BYTES;
        };
        auto load_chunk = [&](int c, int s) {
            uint32_t fb = sb + OFF_MBF + 8u * (uint32_t)s;
            uint32_t Aoff = OFF_T + (uint32_t)s * STAGE;
            mbar_expect_tx(fb, 2u * TILE_BYTES);
            bulk_g2s(sb + Aoff, srcA(c), TILE_BYTES, fb);
            bulk_g2s(sb + Aoff + ASZ, srcB(c), TILE_BYTES, fb);
        };
        load_chunk(0, 0);
        load_chunk(1, 1);
        for (int c = 0; c < nchunk; ++c) {
            const int s = c % 3;
            mbar_wait(sb + OFF_MBF + 8u * (uint32_t)s, (uint32_t)((c / 3) & 1));
            const uint32_t Aoff = OFF_T + (uint32_t)s * STAGE;
            uint64_t ad = make_desc(sb + Aoff);
            uint64_t bd = make_desc(sb + Aoff + ASZ);
            #pragma unroll
            for (int k = 0; k < 4; ++k) {
                bool acc = (c > 0) || (k > 0);
                mma_f16_ss(tmem,       ad + k * 2,        bd + k * 2, IDESC, acc);
                mma_f16_ss(tmem + 256, ad + 1024 + k * 2, bd + k * 2, IDESC, acc);
            }
            tc_commit(sb + OFF_MBE + 8u * (uint32_t)s);
            if (c + 2 < nchunk) {
                const int s2 = (c + 2) % 3;      // stage last used by chunk c-1
                if (c >= 1)
                    mbar_wait(sb + OFF_MBE + 8u * (uint32_t)s2,
                              (uint32_t)(((c - 1) / 3) & 1));
                load_chunk(c + 2, s2);
            }
        }
        // last commits: stage commit index 15 -> parity 1
        mbar_wait(sb + OFF_MBE + 0, 1);
        mbar_wait(sb + OFF_MBE + 8, 1);
        mbar_wait(sb + OFF_MBE + 16, 1);
    }
    __syncthreads();
    TC_FENCE_AFTER();

    // ---- epilogue: 8 warps; half = wid>>2 selects M-half / TMEM 256-col bank
    const float rc = sqrtf(c_ptr[0]);
    const float invrc = 1.0f / rc;
    const int half = wid >> 2, sub = wid & 3;
    const int row = brow + half * 128 + sub * 32 + lane;
    const float cx2 = g_cx2[row];
    const float invd = 1.0f / fmaxf(1.0f - cx2, 1e-15f);
    const float onep = 1.0f + cx2;
    const float two_rc = 2.0f * rc;
    float ysq = 0.f;

    #pragma unroll
    for (int cc = 0; cc < 4; ++cc) {
        const int cb = cc * 64;
        uint32_t d[64];
        TC_LD_X32(d, tmem + half * 256 + cb);
        TC_LD_X32(d + 32, tmem + half * 256 + cb + 32);
        TC_WAIT_LD();
        float* orow = out + (size_t)row * OUT + bcol + cb;
        #pragma unroll
        for (int j = 0; j < 64; j += 4) {
            float yv[4];
            #pragma unroll
            for (int q = 0; q < 4; ++q) {
                int col = cb + j + q;
                float dot = __uint_as_float(d[j + q]);
                float num = fmaf(two_rc * dot, chb[col], -onep * shb[col]);
                float u = num * invd;
                // sinh(g*asinh(u)) = sign(u) * (t^g - t^-g)/2, t = sqrt(u^2+1)+|u|
                float sq = sqrtf(fmaf(u, u, 1.0f));
                float t  = sq + fabsf(u);
                float lt = __logf(t);
                float p  = __expf(g2s[col] * lt);
                float mag = (p - __fdividef(1.0f, p)) * 0.5f * invrc;
                float y = copysignf(mag, u);
                ysq = fmaf(y, y, ysq);
                yv[q] = y;
            }
            *(float4*)(orow + j) = make_float4(yv[0], yv[1], yv[2], yv[3]);
        }
    }
    g_ysq_part[(size_t)row * 4 + blockIdx.x] = ysq;

    TC_FENCE_BEFORE();
    __syncthreads();
    if (wid == 0) tc_dealloc(tmem, 512);

#else  // ------------- SIMT fallback (non-'a' PTX stage; never runs on GB300) -
    float (*As)[128] = (float(*)[128])(smem);
    float (*Bs)[128] = (float(*)[128])(smem + 16 * 128 * 4);

    const int tid = threadIdx.x;
    const int tx = tid & 15, ty = tid >> 4;
    const float cval = c_ptr[0];
    const float rc = sqrtf(cval);
    const float invrc = 1.0f / rc;

    for (int mh = 0; mh < 2; ++mh) {
        const int brow = blockIdx.y * MT + mh * 128;
        for (int nh = 0; nh < 2; ++nh) {
            const int bcol = blockIdx.x * NT + nh * 128;
            float acc[8][8];
            #pragma unroll
            for (int i = 0; i < 8; ++i)
                #pragma unroll
                for (int j = 0; j < 8; ++j) acc[i][j] = 0.f;

            for (int kt = 0; kt < IN; kt += 16) {
                #pragma unroll
                for (int l = 0; l < 2; ++l) {
                    int idx = tid + l * 256;
                    int r = idx >> 2, c4 = (idx & 3) << 2;
                    float4 v = *(const float4*)(X + (size_t)(brow + r) * IN + kt + c4);
                    As[c4 + 0][r] = v.x; As[c4 + 1][r] = v.y;
                    As[c4 + 2][r] = v.z; As[c4 + 3][r] = v.w;
                }
                #pragma unroll
                for (int l = 0; l < 2; ++l) {
                    int idx = tid + l * 256;
                    int r = idx >> 5, c4 = (idx & 31) << 2;
                    *(float4*)(&Bs[r][c4]) =
                        *(const float4*)(W + (size_t)(kt + r) * OUT + bcol + c4);
                }
                __syncthreads();
                #pragma unroll
                for (int k = 0; k < 16; ++k) {
                    float a[8], b[8];
                    #pragma unroll
                    for (int q = 0; q < 8; ++q) a[q] = As[k][ty * 8 + q];
                    #pragma unroll
                    for (int q = 0; q < 8; ++q) b[q] = Bs[k][tx * 8 + q];
                    #pragma unroll
                    for (int i = 0; i < 8; ++i)
                        #pragma unroll
                        for (int j = 0; j < 8; ++j)
                            acc[i][j] = fmaf(a[i], b[j], acc[i][j]);
                }
                __syncthreads();
            }
            #pragma unroll
            for (int i = 0; i < 8; ++i) {
                int n = brow + ty * 8 + i;
                float cx2 = g_cx2[n];
                float invd = 1.0f / fmaxf(1.0f - cx2, 1e-15f);
                float onep = 1.0f + cx2;
                float y[8];
                float ysq = 0.f;
                #pragma unroll
                for (int j = 0; j < 8; ++j) {
                    int o = bcol + tx * 8 + j;
                    float num = 2.0f * rc * acc[i][j] * g_colscale[o] * g_coshb[o]
                                - onep * g_sinhb[o];
                    float a = 2.0f * wgp[o] * asinhf(num * invd);
                    y[j] = sinhf(a) * invrc;
                    ysq = fmaf(y[j], y[j], ysq);
                }
                atomicAdd(&g_ysq_part[(size_t)n * 4 + blockIdx.x], ysq);
                float* orow = out + (size_t)n * OUT + bcol + tx * 8;
                *(float4*)(orow)     = make_float4(y[0], y[1], y[2], y[3]);
                *(float4*)(orow + 4) = make_float4(y[4], y[5], y[6], y[7]);
            }
            __syncthreads();
        }
    }
#endif
}

// ---------------- rescale: gyro-half map + ball projection -------------------
__global__ void rescale_kernel(float* __restrict__ out,
                               const float* __restrict__ c_ptr, int OUT) {
    int row = blockIdx.x;
    float tot = g_ysq_part[(size_t)row * 4 + 0] + g_ysq_part[(size_t)row * 4 + 1]
              + g_ysq_part[(size_t)row * 4 + 2] + g_ysq_part[(size_t)row * 4 + 3];
    float c = c_ptr[0];
    float denom = 1.0f + sqrtf(1.0f + c * tot);
    float scale = 1.0f / denom;
    float norm = fmaxf(sqrtf(tot) * scale, 1e-15f);
    float kk = -c;
    float maxnorm = (1.0f - 0.004f) * rsqrtf(fmaxf(fabsf(kk), 1e-15f));
    if (!(kk < 0.f)) maxnorm = 1e15f;
    if (norm > maxnorm) scale *= maxnorm / norm;

    float4* yr = (float4*)(out + (size_t)row * OUT);
    int n4 = OUT >> 2;
    for (int i = threadIdx.x; i < n4; i += blockDim.x) {
        float4 v = yr[i];
        v.x *= scale; v.y *= scale; v.z *= scale; v.w *= scale;
        yr[i] = v;
    }
}

// ---------------------------------------------------------------------------
extern "C" void kernel_launch(void* const* d_in, const int* in_sizes, int n_in,
                              void* d_out, int out_size) {
    const float* x    = (const float*)d_in[0];
    const float* w    = (const float*)d_in[1];
    const float* wg   = (const float*)d_in[2];
    const float* bias = (const float*)d_in[3];
    const float* c    = (const float*)d_in[4];
    float* out = (float*)d_out;

    int OUT = in_sizes[2];
    int IN  = in_sizes[1] / OUT;
    int N   = in_sizes[0] / IN;

    static int smem_set = 0;
    if (!smem_set) {
        cudaFuncSetAttribute(gemm_tc_kernel, cudaFuncAttributeMaxDynamicSharedMemorySize,
                             SMEM_BYTES);
        smem_set = 1;
    }

    prep_kernel<<<OUT, 256>>>(w, bias, c, IN, OUT);
    convert_w_kernel<<<dim3(OUT / 32, IN / 32), dim3(32, 32)>>>(w, IN, OUT);
    convert_x_kernel<<<N, 128>>>(x, c, IN);
    dim3 grid(OUT / NT, N / MT);
    gemm_tc_kernel<<<grid, 256, SMEM_BYTES>>>(x, w, wg, c, out, N, IN, OUT);
    rescale_kernel<<<N, 256>>>(out, c, OUT);
}